// round 16
// baseline (speedup 1.0000x reference)
#include <cuda_runtime.h>
#include <cuda_fp16.h>
#include <cstdint>

// Fixed problem shapes
#define BB    16
#define DC    16
#define ND    1024
#define CIN   64
#define COUT  128
#define NN    4096
#define KW    7
#define LT    64             // l-tile per CTA
#define NCH   8              // K chunks (8 channels each)
#define NTHR  256            // 8 warps, warp tile 32o x 32l

// Scratch (device globals; no allocation allowed)
__device__ float g_z[BB*CIN*ND];
__device__ float g_scale[BB*CIN];
__device__ float g_shift[BB*CIN];
__device__ __align__(16) __half g_wH[NCH*COUT*64];   // [ch][o][col], col=cc*8+k

// ---------------- smem layout (bytes) ----------------
// W/M tiles: 128B rows, XOR swizzle col16' = col16 ^ (row&7) -> conflict-free
#define OFF_E    0                    // E = exp(2*xs) fp32 [64][70] = 17920
#define OFF_XH   17920                // x  fp16 [64][70] = 8960
#define OFF_ST   26880                // 2 stages x (W 16384 + M 8192)
#define T_W      0
#define T_M      16384
#define STAGE_BYTES 24576
#define SMEM_TOTAL (OFF_ST + 2*STAGE_BYTES)   // 76032 -> 3 CTAs/SM

#define CP16(dst, src) asm volatile("cp.async.cg.shared.global [%0], [%1], 16;" :: "r"(dst), "l"(src) : "memory")
#define CPCOMMIT()     asm volatile("cp.async.commit_group;" ::: "memory")
#define CPWAIT0()      asm volatile("cp.async.wait_group 0;" ::: "memory")

__device__ __forceinline__ uint32_t smem_u32(const void* p) {
    uint32_t a;
    asm("{ .reg .u64 t; cvta.to.shared.u64 t, %1; cvt.u32.u64 %0, t; }" : "=r"(a) : "l"(p));
    return a;
}
__device__ __forceinline__ float rcpa(float x) {
    float r;
    asm("rcp.approx.f32 %0, %1;" : "=f"(r) : "f"(x));
    return r;
}
__device__ __forceinline__ float ex2a(float x) {
    float r;
    asm("ex2.approx.f32 %0, %1;" : "=f"(r) : "f"(x));
    return r;
}
// pack(first, second) -> f16x2, first in bits[15:0]
__device__ __forceinline__ uint32_t packh(float a0, float a1) {
    uint32_t r;
    asm("cvt.rn.f16x2.f32 %0, %1, %2;" : "=r"(r) : "f"(a1), "f"(a0));
    return r;
}
#define LDSM4(r, a) \
    asm volatile("ldmatrix.sync.aligned.m8n8.x4.shared.b16 {%0,%1,%2,%3}, [%4];" \
        : "=r"((r)[0]), "=r"((r)[1]), "=r"((r)[2]), "=r"((r)[3]) : "r"(a))
#define MMAH(d, a, b0, b1) \
    asm volatile("mma.sync.aligned.m16n8k16.row.col.f32.f16.f16.f32 " \
        "{%0,%1,%2,%3},{%4,%5,%6,%7},{%8,%9},{%0,%1,%2,%3};" \
        : "+f"((d)[0]), "+f"((d)[1]), "+f"((d)[2]), "+f"((d)[3]) \
        : "r"((a)[0]), "r"((a)[1]), "r"((a)[2]), "r"((a)[3]), "r"(b0), "r"(b1))

// ---------------- kernel 1: fused z + stats + wsplit ----------------
__global__ void k_prep(const float* __restrict__ deep, const float* __restrict__ conv_w,
                       const float* __restrict__ conv_b, const float* __restrict__ fc_w) {
    __shared__ float sz[ND];
    __shared__ float cw[DC];
    __shared__ float red1[8], red2[8];
    int bc  = blockIdx.x;
    int c   = bc & (CIN-1);
    int b   = bc >> 6;
    int tid = threadIdx.x;
    if (tid < 64) {
        int idx = bc*64 + tid;
        int ch  = idx >> 13;
        int o   = (idx >> 6) & 127;
        int col = idx & 63;
        int cc = col >> 3, k = col & 7;
        float v = (k < KW) ? fc_w[o*(CIN*KW) + (ch*8 + cc)*KW + k] : 0.f;
        g_wH[idx] = __float2half_rn(v);
    }
    if (tid < DC) cw[tid] = conv_w[c*DC + tid];
    __syncthreads();
    const float* dp = deep + (size_t)b*DC*ND;
    float* zrow = g_z + (size_t)bc*ND;
    for (int m = tid; m < ND; m += 256) {
        float acc = 0.f;
        #pragma unroll
        for (int d = 0; d < DC; ++d) acc += cw[d] * dp[(size_t)d*ND + m];
        sz[m] = acc;
        zrow[m] = acc;
    }
    __syncthreads();
    float bias = conv_b[c];
    float s1 = 0.f, s2 = 0.f;
    for (int n = tid; n < NN; n += 256) {
        float src = 0.25f*(float)n - 0.375f;
        src = fminf(fmaxf(src, 0.f), (float)(ND-1));
        int lo = (int)src;
        int hi = min(lo + 1, ND-1);
        float w = src - (float)lo;
        float v = sz[lo]*(1.f - w) + sz[hi]*w + bias;
        s1 += v; s2 += v*v;
    }
    #pragma unroll
    for (int off = 16; off; off >>= 1) {
        s1 += __shfl_down_sync(0xffffffffu, s1, off);
        s2 += __shfl_down_sync(0xffffffffu, s2, off);
    }
    if ((tid & 31) == 0) { red1[tid>>5] = s1; red2[tid>>5] = s2; }
    __syncthreads();
    if (tid == 0) {
        float t1 = 0.f, t2 = 0.f;
        #pragma unroll
        for (int i = 0; i < 8; ++i) { t1 += red1[i]; t2 += red2[i]; }
        float mean = t1 / (float)NN;
        float var  = (t2 - (float)NN*mean*mean) / (float)(NN-1);
        float sc   = 0.5f / (var + 1e-9f);
        g_scale[bc] = sc;
        g_shift[bc] = -sc * mean;
    }
}

// W chunk -> swizzled smem (4 cp.async per thread)
__device__ __forceinline__ void load_w(uint32_t dstbase, int ch, int tid) {
    const char* src = (const char*)(g_wH + (size_t)ch*COUT*64);
    #pragma unroll
    for (int j = 0; j < 4; ++j) {
        int idx = tid + j*NTHR;          // 0..1023
        int o = idx >> 3, seg = idx & 7;
        CP16(dstbase + (uint32_t)(o*128 + ((seg ^ (o & 7)) << 4)), src + (size_t)idx*16);
    }
    CPCOMMIT();
}

// one build task: r_k = E_k*E_3/(E_k+E_3)^2; writes 8 packed halves (last = 0)
__device__ __forceinline__ void build_task(char* stage, uint32_t soff,
                                           const float* Ep, const __half* xhp) {
    float E3 = Ep[3];
    #define RT(i) ({ float e_ = Ep[i]; float su_ = e_ + E3; (e_ * E3) * rcpa(su_ * su_); })
    float r0 = RT(0), r1 = RT(1), r2 = RT(2);
    float r4 = RT(4), r5 = RT(5), r6 = RT(6);
    #undef RT
    float den = ((r0 + r1) + (r2 + 0.25f)) + ((r4 + r5) + r6);
    float inv = rcpa(den);
    float m0v = __half2float(xhp[0]) * (r0 * inv);
    float m1v = __half2float(xhp[1]) * (r1 * inv);
    float m2v = __half2float(xhp[2]) * (r2 * inv);
    float m3v = __half2float(xhp[3]) * (0.25f * inv);
    float m4v = __half2float(xhp[4]) * (r4 * inv);
    float m5v = __half2float(xhp[5]) * (r5 * inv);
    float m6v = __half2float(xhp[6]) * (r6 * inv);
    uint32_t h0 = packh(m0v, m1v), h1 = packh(m2v, m3v);
    uint32_t h2 = packh(m4v, m5v), h3 = packh(m6v, 0.f);
    *(uint4*)(stage + soff) = make_uint4(h0, h1, h2, h3);
}

// ---------------- kernel 2: interleaved build + HMMA, 3 CTAs/SM ----------------
// grid (NN/LT=64, BB=16) = 1024 CTAs, 256 threads, warp tile 32o x 32l.
__global__ __launch_bounds__(NTHR, 3)
void k_tc(const float* __restrict__ x, const float* __restrict__ conv_b,
          float* __restrict__ out) {
    extern __shared__ __align__(16) char smem[];
    const uint32_t sb = smem_u32(smem);
    const int tid  = threadIdx.x;
    const int lane = tid & 31;
    const int wid  = tid >> 5;
    const int b    = blockIdx.y;
    const int l0   = blockIdx.x * LT;

    float*  sE  = (float*) (smem + OFF_E);
    __half* sxh = (__half*)(smem + OFF_XH);

    load_w(sb + OFF_ST, 0, tid);        // W0 -> stage 0 (async)

    // ---- stage E = exp(2*xs) fp32 + x fp16; thread -> (c = tid>>2, i stride 4) ----
    {
        const int c  = tid >> 2;        // 0..63
        const int i0 = tid & 3;
        const int bc = b*CIN + c;
        const float* zrow = g_z + (size_t)bc*ND;
        const float* xg   = x + (size_t)bc*NN;
        const float LOG2E2 = 2.8853900817779268f;   // 2*log2(e)
        const float sc2 = g_scale[bc] * LOG2E2;
        const float sh2 = g_shift[bc] * LOG2E2;
        const float cb  = conv_b[c];
        float*  Erow = sE  + c*70;
        __half* xrow = sxh + c*70;
        #pragma unroll 2
        for (int i = i0; i < 70; i += 4) {
            int p = l0 - 3 + i;
            if (p < 0)   p = -p;
            if (p >= NN) p = 2*NN - 2 - p;
            float src = 0.25f*(float)p - 0.375f;
            src = fminf(fmaxf(src, 0.f), (float)(ND-1));
            int lo = (int)src;
            int hi = min(lo + 1, ND-1);
            float w = src - (float)lo;
            float v = zrow[lo]*(1.f - w) + zrow[hi]*w + cb;   // y
            Erow[i] = ex2a(sc2 * v + sh2);                    // exp(2*xs)
            xrow[i] = __float2half_rn(xg[p]);
        }
    }

    // ---- loop-invariant build state (l, cc fixed across chunks) ----
    const int bl   = tid & 63;
    const int cc_a = tid >> 6;          // 0..3 (task b uses cc_a+4)
    const uint32_t soff_a = (uint32_t)(T_M + bl*128 + (((unsigned)cc_a ^ (unsigned)(bl & 7)) << 4));
    // (cc_a+4)^s == (cc_a^s)^4 since cc_a<4 -> soff_b = soff_a ^ 0x40
    const float*  pE = sE  + cc_a*70 + bl;      // advance +560 per chunk
    const __half* pX = sxh + cc_a*70 + bl;

    __syncthreads();

    // prologue build chunk 0
    build_task(smem + OFF_ST, soff_a,        pE,       pX);
    build_task(smem + OFF_ST, soff_a ^ 0x40, pE + 280, pX + 280);
    const float*  pEn = pE + 560;
    const __half* pXn = pX + 560;
    CPWAIT0();
    __syncthreads();                    // stage 0 ready

    // warp tile 32o x 32l: 4 warps across o, 2 across l
    const int m0 = (wid & 3) * 32;
    const int n0 = (wid >> 2) * 32;
    const uint32_t vA = (uint32_t)(((lane >> 4) & 1) ^ (lane & 7));
    const uint32_t vB = (uint32_t)(((lane >> 3) & 1) ^ (lane & 7));
    const uint32_t rowA = (uint32_t)((m0 + (lane & 15)) * 128);
    const uint32_t rowB = (uint32_t)((n0 + (lane & 7) + 8*((lane >> 4) & 1)) * 128);

    float acc[2][4][4];
    #pragma unroll
    for (int i = 0; i < 2; ++i)
        #pragma unroll
        for (int n = 0; n < 4; ++n)
            #pragma unroll
            for (int r = 0; r < 4; ++r) acc[i][n][r] = 0.f;

    #pragma unroll 1
    for (int ch = 0; ch < NCH; ++ch) {
        const int s = ch & 1;
        const uint32_t stc = sb + (uint32_t)(OFF_ST + s*STAGE_BYTES);
        // produce next stage first (fills MMA stall slots)
        if (ch + 1 < NCH) {
            char* stn = smem + OFF_ST + (s^1)*STAGE_BYTES;
            load_w(sb + (uint32_t)(OFF_ST + (s^1)*STAGE_BYTES), ch + 1, tid);
            build_task(stn, soff_a,        pEn,       pXn);
            build_task(stn, soff_a ^ 0x40, pEn + 280, pXn + 280);
            pEn += 560; pXn += 560;
        }
        // MMA on current stage
        const uint32_t bA = stc + T_W + rowA;
        const uint32_t bB = stc + T_M + rowB;
        #pragma unroll
        for (int ks = 0; ks < 4; ++ks) {
            uint32_t a0[4], a1[4], bm[4], bm2[4];
            const uint32_t cA = (vA ^ (uint32_t)(2*ks)) << 4;
            const uint32_t cB = (vB ^ (uint32_t)(2*ks)) << 4;
            LDSM4(a0, bA + cA);
            LDSM4(a1, bA + cA + 16*128);
            LDSM4(bm,  bB + cB);
            LDSM4(bm2, bB + cB + 16*128);
            MMAH(acc[0][0], a0, bm[0],  bm[1]);
            MMAH(acc[0][1], a0, bm[2],  bm[3]);
            MMAH(acc[0][2], a0, bm2[0], bm2[1]);
            MMAH(acc[0][3], a0, bm2[2], bm2[3]);
            MMAH(acc[1][0], a1, bm[0],  bm[1]);
            MMAH(acc[1][1], a1, bm[2],  bm[3]);
            MMAH(acc[1][2], a1, bm2[0], bm2[1]);
            MMAH(acc[1][3], a1, bm2[2], bm2[3]);
        }
        if (ch + 1 < NCH) CPWAIT0();
        __syncthreads();
    }

    // ---- epilogue: direct STG.64 ----
    const int g = lane >> 2, tq = lane & 3;
    float* outb = out + (size_t)b*COUT*NN + l0;
    #pragma unroll
    for (int i = 0; i < 2; ++i) {
        int o = m0 + i*16 + g;
        #pragma unroll
        for (int n = 0; n < 4; ++n) {
            int lp = n0 + n*8 + 2*tq;
            *(float2*)(outb + (size_t)o*NN + lp)     = make_float2(acc[i][n][0], acc[i][n][1]);
            *(float2*)(outb + (size_t)(o+8)*NN + lp) = make_float2(acc[i][n][2], acc[i][n][3]);
        }
    }
}

// ---------------- launch ----------------
extern "C" void kernel_launch(void* const* d_in, const int* in_sizes, int n_in,
                              void* d_out, int out_size) {
    const float* deep   = (const float*)d_in[0];
    const float* x      = (const float*)d_in[1];
    const float* conv_w = (const float*)d_in[2];
    const float* conv_b = (const float*)d_in[3];
    const float* fc_w   = (const float*)d_in[4];
    float* out = (float*)d_out;

    cudaFuncSetAttribute(k_tc, cudaFuncAttributeMaxDynamicSharedMemorySize, SMEM_TOTAL);

    k_prep<<<BB*CIN, 256>>>(deep, conv_w, conv_b, fc_w);
    k_tc  <<<dim3(NN/LT, BB), NTHR, SMEM_TOTAL>>>(x, conv_b, out);
}

// round 17
// speedup vs baseline: 1.0275x; 1.0275x over previous
#include <cuda_runtime.h>
#include <cuda_fp16.h>
#include <cstdint>

// Fixed problem shapes
#define BB    16
#define DC    16
#define ND    1024
#define CIN   64
#define COUT  128
#define NN    4096
#define KW    7
#define LT    64             // l-tile per CTA
#define NCH   8              // K chunks (8 channels each)
#define NTHR  256            // 8 warps, warp tile 32o x 32l

// Scratch (device globals; no allocation allowed)
__device__ float g_z[BB*CIN*ND];
__device__ float g_scale[BB*CIN];
__device__ float g_shift[BB*CIN];
// W pre-packed as m16n8k16 A-fragments: [ch][ob][ks][lane] uint4 (a0,a1,a2,a3)
__device__ __align__(16) uint4 g_wF[NCH*8*4*32];     // 8192 uint4 = 128KB

// ---------------- smem layout (bytes) ----------------
// M tiles: 128B rows, XOR swizzle col16' = col16 ^ (row&7) -> conflict-free
#define OFF_E    0                    // E = exp(2*xs) fp32 [64][70] = 17920
#define OFF_XH   17920                // x  fp16 [64][70] = 8960
#define OFF_ST   26880                // 2 stages x M 8192
#define STAGE_BYTES 8192
#define SMEM_TOTAL (OFF_ST + 2*STAGE_BYTES)   // 43264 -> 3 CTAs/SM

__device__ __forceinline__ uint32_t smem_u32(const void* p) {
    uint32_t a;
    asm("{ .reg .u64 t; cvta.to.shared.u64 t, %1; cvt.u32.u64 %0, t; }" : "=r"(a) : "l"(p));
    return a;
}
__device__ __forceinline__ float rcpa(float x) {
    float r;
    asm("rcp.approx.f32 %0, %1;" : "=f"(r) : "f"(x));
    return r;
}
__device__ __forceinline__ float ex2a(float x) {
    float r;
    asm("ex2.approx.f32 %0, %1;" : "=f"(r) : "f"(x));
    return r;
}
// pack(first, second) -> f16x2, first in bits[15:0]
__device__ __forceinline__ uint32_t packh(float a0, float a1) {
    uint32_t r;
    asm("cvt.rn.f16x2.f32 %0, %1, %2;" : "=r"(r) : "f"(a1), "f"(a0));
    return r;
}
#define LDSM4(r, a) \
    asm volatile("ldmatrix.sync.aligned.m8n8.x4.shared.b16 {%0,%1,%2,%3}, [%4];" \
        : "=r"((r)[0]), "=r"((r)[1]), "=r"((r)[2]), "=r"((r)[3]) : "r"(a))
// A operand from a uint4 register (a0..a3 = .x...w)
#define MMAH4(d, v, b0, b1) \
    asm volatile("mma.sync.aligned.m16n8k16.row.col.f32.f16.f16.f32 " \
        "{%0,%1,%2,%3},{%4,%5,%6,%7},{%8,%9},{%0,%1,%2,%3};" \
        : "+f"((d)[0]), "+f"((d)[1]), "+f"((d)[2]), "+f"((d)[3]) \
        : "r"((v).x), "r"((v).y), "r"((v).z), "r"((v).w), "r"(b0), "r"(b1))

// ---------------- kernel 1: fused z + stats + W-fragment pack ----------------
__global__ void k_prep(const float* __restrict__ deep, const float* __restrict__ conv_w,
                       const float* __restrict__ conv_b, const float* __restrict__ fc_w) {
    __shared__ float sz[ND];
    __shared__ float cw[DC];
    __shared__ float red1[8], red2[8];
    int bc  = blockIdx.x;
    int c   = bc & (CIN-1);
    int b   = bc >> 6;
    int tid = threadIdx.x;
    // pack fc_w into m16n8k16 A-fragment layout (8192 uint4 over 1024 blocks)
    if (tid < 8) {
        int idx  = bc*8 + tid;            // 0..8191
        int lane = idx & 31;
        int ks   = (idx >> 5) & 3;
        int ob   = (idx >> 7) & 7;
        int ch   = idx >> 10;
        int g  = lane >> 2;
        int t2 = (lane & 3) * 2;
        int o0 = ob*16 + g;
        int kc = ks*16 + t2;
        auto wv = [&](int orow, int kcol) -> float {
            int cc = kcol >> 3, k = kcol & 7;
            return (k < KW) ? fc_w[orow*(CIN*KW) + (ch*8 + cc)*KW + k] : 0.f;
        };
        uint4 u;
        u.x = packh(wv(o0,     kc),     wv(o0,     kc + 1));
        u.y = packh(wv(o0 + 8, kc),     wv(o0 + 8, kc + 1));
        u.z = packh(wv(o0,     kc + 8), wv(o0,     kc + 9));
        u.w = packh(wv(o0 + 8, kc + 8), wv(o0 + 8, kc + 9));
        g_wF[idx] = u;
    }
    if (tid < DC) cw[tid] = conv_w[c*DC + tid];
    __syncthreads();
    const float* dp = deep + (size_t)b*DC*ND;
    float* zrow = g_z + (size_t)bc*ND;
    for (int m = tid; m < ND; m += 256) {
        float acc = 0.f;
        #pragma unroll
        for (int d = 0; d < DC; ++d) acc += cw[d] * dp[(size_t)d*ND + m];
        sz[m] = acc;
        zrow[m] = acc;
    }
    __syncthreads();
    float bias = conv_b[c];
    float s1 = 0.f, s2 = 0.f;
    for (int n = tid; n < NN; n += 256) {
        float src = 0.25f*(float)n - 0.375f;
        src = fminf(fmaxf(src, 0.f), (float)(ND-1));
        int lo = (int)src;
        int hi = min(lo + 1, ND-1);
        float w = src - (float)lo;
        float v = sz[lo]*(1.f - w) + sz[hi]*w + bias;
        s1 += v; s2 += v*v;
    }
    #pragma unroll
    for (int off = 16; off; off >>= 1) {
        s1 += __shfl_down_sync(0xffffffffu, s1, off);
        s2 += __shfl_down_sync(0xffffffffu, s2, off);
    }
    if ((tid & 31) == 0) { red1[tid>>5] = s1; red2[tid>>5] = s2; }
    __syncthreads();
    if (tid == 0) {
        float t1 = 0.f, t2 = 0.f;
        #pragma unroll
        for (int i = 0; i < 8; ++i) { t1 += red1[i]; t2 += red2[i]; }
        float mean = t1 / (float)NN;
        float var  = (t2 - (float)NN*mean*mean) / (float)(NN-1);
        float sc   = 0.5f / (var + 1e-9f);
        g_scale[bc] = sc;
        g_shift[bc] = -sc * mean;
    }
}

// one build task: r_k = E_k*E_3/(E_k+E_3)^2; writes 8 packed halves (last = 0)
__device__ __forceinline__ void build_task(char* stage, uint32_t soff,
                                           const float* Ep, const __half* xhp) {
    float E3 = Ep[3];
    #define RT(i) ({ float e_ = Ep[i]; float su_ = e_ + E3; (e_ * E3) * rcpa(su_ * su_); })
    float r0 = RT(0), r1 = RT(1), r2 = RT(2);
    float r4 = RT(4), r5 = RT(5), r6 = RT(6);
    #undef RT
    float den = ((r0 + r1) + (r2 + 0.25f)) + ((r4 + r5) + r6);
    float inv = rcpa(den);
    float m0v = __half2float(xhp[0]) * (r0 * inv);
    float m1v = __half2float(xhp[1]) * (r1 * inv);
    float m2v = __half2float(xhp[2]) * (r2 * inv);
    float m3v = __half2float(xhp[3]) * (0.25f * inv);
    float m4v = __half2float(xhp[4]) * (r4 * inv);
    float m5v = __half2float(xhp[5]) * (r5 * inv);
    float m6v = __half2float(xhp[6]) * (r6 * inv);
    uint32_t h0 = packh(m0v, m1v), h1 = packh(m2v, m3v);
    uint32_t h2 = packh(m4v, m5v), h3 = packh(m6v, 0.f);
    *(uint4*)(stage + soff) = make_uint4(h0, h1, h2, h3);
}

// ---------------- kernel 2: interleaved build + HMMA, A-frags via LDG ----------------
// grid (NN/LT=64, BB=16) = 1024 CTAs, 256 threads, warp tile 32o x 32l, 3 CTAs/SM.
__global__ __launch_bounds__(NTHR, 3)
void k_tc(const float* __restrict__ x, const float* __restrict__ conv_b,
          float* __restrict__ out) {
    extern __shared__ __align__(16) char smem[];
    const uint32_t sb = smem_u32(smem);
    const int tid  = threadIdx.x;
    const int lane = tid & 31;
    const int wid  = tid >> 5;
    const int b    = blockIdx.y;
    const int l0   = blockIdx.x * LT;

    float*  sE  = (float*) (smem + OFF_E);
    __half* sxh = (__half*)(smem + OFF_XH);

    // ---- A-fragment prefetch pointer: ob0 = (wid&3)*2, stride 1024/ch, 128/ob ----
    const uint4* wfp = g_wF + (wid & 3)*256 + lane;
    uint4 aw0[4], aw1[4];
    #pragma unroll
    for (int ks = 0; ks < 4; ++ks) {     // chunk 0 prefetch (lands during staging)
        aw0[ks] = wfp[ks*32];
        aw1[ks] = wfp[128 + ks*32];
    }

    // ---- stage E = exp(2*xs) fp32 + x fp16; thread -> (c = tid>>2, i stride 4) ----
    {
        const int c  = tid >> 2;        // 0..63
        const int i0 = tid & 3;
        const int bc = b*CIN + c;
        const float* zrow = g_z + (size_t)bc*ND;
        const float* xg   = x + (size_t)bc*NN;
        const float LOG2E2 = 2.8853900817779268f;   // 2*log2(e)
        const float sc2 = g_scale[bc] * LOG2E2;
        const float sh2 = g_shift[bc] * LOG2E2;
        const float cb  = conv_b[c];
        float*  Erow = sE  + c*70;
        __half* xrow = sxh + c*70;
        #pragma unroll 2
        for (int i = i0; i < 70; i += 4) {
            int p = l0 - 3 + i;
            if (p < 0)   p = -p;
            if (p >= NN) p = 2*NN - 2 - p;
            float src = 0.25f*(float)p - 0.375f;
            src = fminf(fmaxf(src, 0.f), (float)(ND-1));
            int lo = (int)src;
            int hi = min(lo + 1, ND-1);
            float w = src - (float)lo;
            float v = zrow[lo]*(1.f - w) + zrow[hi]*w + cb;   // y
            Erow[i] = ex2a(sc2 * v + sh2);                    // exp(2*xs)
            xrow[i] = __float2half_rn(xg[p]);
        }
    }

    // ---- loop-invariant build state (l, cc fixed across chunks) ----
    const int bl   = tid & 63;
    const int cc_a = tid >> 6;          // 0..3 (task b uses cc_a+4)
    const uint32_t soff_a = (uint32_t)(bl*128 + (((unsigned)cc_a ^ (unsigned)(bl & 7)) << 4));
    const float*  pE = sE  + cc_a*70 + bl;      // advance +560 per chunk
    const __half* pX = sxh + cc_a*70 + bl;

    __syncthreads();

    // prologue build chunk 0
    build_task(smem + OFF_ST, soff_a,        pE,       pX);
    build_task(smem + OFF_ST, soff_a ^ 0x40, pE + 280, pX + 280);
    const float*  pEn = pE + 560;
    const __half* pXn = pX + 560;
    __syncthreads();                    // stage 0 ready

    // warp tile 32o x 32l: 4 warps across o, 2 across l
    const int m0 = (wid & 3) * 32;
    const int n0 = (wid >> 2) * 32;
    const uint32_t vB = (uint32_t)(((lane >> 3) & 1) ^ (lane & 7));
    const uint32_t rowB = (uint32_t)((n0 + (lane & 7) + 8*((lane >> 4) & 1)) * 128);

    float acc[2][4][4];
    #pragma unroll
    for (int i = 0; i < 2; ++i)
        #pragma unroll
        for (int n = 0; n < 4; ++n)
            #pragma unroll
            for (int r = 0; r < 4; ++r) acc[i][n][r] = 0.f;

    #pragma unroll 1
    for (int ch = 0; ch < NCH; ++ch) {
        const int s = ch & 1;
        // MMA on current stage (a-frags already in registers)
        const uint32_t bB = sb + (uint32_t)(OFF_ST + s*STAGE_BYTES) + rowB;
        #pragma unroll
        for (int ks = 0; ks < 4; ++ks) {
            uint32_t bm[4], bm2[4];
            const uint32_t cB = (vB ^ (uint32_t)(2*ks)) << 4;
            LDSM4(bm,  bB + cB);
            LDSM4(bm2, bB + cB + 16*128);
            MMAH4(acc[0][0], aw0[ks], bm[0],  bm[1]);
            MMAH4(acc[0][1], aw0[ks], bm[2],  bm[3]);
            MMAH4(acc[0][2], aw0[ks], bm2[0], bm2[1]);
            MMAH4(acc[0][3], aw0[ks], bm2[2], bm2[3]);
            MMAH4(acc[1][0], aw1[ks], bm[0],  bm[1]);
            MMAH4(acc[1][1], aw1[ks], bm[2],  bm[3]);
            MMAH4(acc[1][2], aw1[ks], bm2[0], bm2[1]);
            MMAH4(acc[1][3], aw1[ks], bm2[2], bm2[3]);
        }
        if (ch + 1 < NCH) {
            // prefetch next chunk's A-frags (latency covered by build + sync)
            const uint4* p = wfp + (ch + 1)*1024;
            #pragma unroll
            for (int ks = 0; ks < 4; ++ks) {
                aw0[ks] = p[ks*32];
                aw1[ks] = p[128 + ks*32];
            }
            // build next chunk's M tile into the other stage
            char* stn = smem + OFF_ST + (s^1)*STAGE_BYTES;
            build_task(stn, soff_a,        pEn,       pXn);
            build_task(stn, soff_a ^ 0x40, pEn + 280, pXn + 280);
            pEn += 560; pXn += 560;
        }
        __syncthreads();
    }

    // ---- epilogue: direct STG.64 ----
    const int g = lane >> 2, tq = lane & 3;
    float* outb = out + (size_t)b*COUT*NN + l0;
    #pragma unroll
    for (int i = 0; i < 2; ++i) {
        int o = m0 + i*16 + g;
        #pragma unroll
        for (int n = 0; n < 4; ++n) {
            int lp = n0 + n*8 + 2*tq;
            *(float2*)(outb + (size_t)o*NN + lp)     = make_float2(acc[i][n][0], acc[i][n][1]);
            *(float2*)(outb + (size_t)(o+8)*NN + lp) = make_float2(acc[i][n][2], acc[i][n][3]);
        }
    }
}

// ---------------- launch ----------------
extern "C" void kernel_launch(void* const* d_in, const int* in_sizes, int n_in,
                              void* d_out, int out_size) {
    const float* deep   = (const float*)d_in[0];
    const float* x      = (const float*)d_in[1];
    const float* conv_w = (const float*)d_in[2];
    const float* conv_b = (const float*)d_in[3];
    const float* fc_w   = (const float*)d_in[4];
    float* out = (float*)d_out;

    cudaFuncSetAttribute(k_tc, cudaFuncAttributeMaxDynamicSharedMemorySize, SMEM_TOTAL);

    k_prep<<<BB*CIN, 256>>>(deep, conv_w, conv_b, fc_w);
    k_tc  <<<dim3(NN/LT, BB), NTHR, SMEM_TOTAL>>>(x, conv_b, out);
}